// round 2
// baseline (speedup 1.0000x reference)
#include <cuda_runtime.h>

#define DV   512
#define NB   32
#define NS   1024
#define NBS  (NB*NS)       // 32768
#define NN   2048
#define KCONV 1536         // 3*512

// ---------------- scratch (static device globals; no allocs) ----------------
__device__ float g_X0[NBS*DV];   // embedded input (masked)
__device__ float g_Y1[NBS*DV];   // conv1 out; later reused for h (hproj out)
__device__ float g_Y2[NBS*DV];   // conv2 out; LN writes in place
__device__ float g_Xs[NN*DV];    // inv_sqrt[j] * embed[sub_nodes[j]]
__device__ float g_AX[NN*DV];    // A_norm @ X
__device__ float g_Hc[NN*DV];    // candidate embeddings H
__device__ float g_inv[NN];      // inv_sqrt of degrees

// ---------------- small kernels ----------------

__global__ void k_deg(const float* __restrict__ A, float* __restrict__ invs) {
    int i = blockIdx.x;
    int tid = threadIdx.x;
    float s = 0.f;
    const float* row = A + (size_t)i * NN;
    for (int j = tid; j < NN; j += 256) s += row[j];
    __shared__ float sh[8];
    #pragma unroll
    for (int o = 16; o > 0; o >>= 1) s += __shfl_down_sync(0xffffffffu, s, o);
    if ((tid & 31) == 0) sh[tid >> 5] = s;
    __syncthreads();
    if (tid == 0) {
        float t = 0.f;
        #pragma unroll
        for (int w = 0; w < 8; w++) t += sh[w];
        t += 1.0f;                    // + identity
        t = fmaxf(t, 1e-6f);          // clip
        invs[i] = rsqrtf(t);
    }
}

__global__ void k_gather_xs(const int* __restrict__ sub_nodes,
                            const float* __restrict__ embed,
                            const float* __restrict__ invs,
                            float* __restrict__ Xs) {
    int j = blockIdx.x;
    int idx = sub_nodes[j];
    float sc = invs[j];
    const float4* src = (const float4*)(embed + (size_t)idx * DV);
    float4* dst = (float4*)(Xs + (size_t)j * DV);
    for (int t = threadIdx.x; t < DV / 4; t += blockDim.x) {
        float4 v = src[t];
        v.x *= sc; v.y *= sc; v.z *= sc; v.w *= sc;
        dst[t] = v;
    }
}

__global__ void k_embed_gather(const int* __restrict__ x_in,
                               const int* __restrict__ mask,
                               const float* __restrict__ embed,
                               float* __restrict__ X0) {
    int r = blockIdx.x;
    int idx = x_in[r];
    float m = (mask[r] != 0) ? 1.f : 0.f;
    const float4* src = (const float4*)(embed + (size_t)idx * DV);
    float4* dst = (float4*)(X0 + (size_t)r * DV);
    for (int t = threadIdx.x; t < DV / 4; t += blockDim.x) {
        float4 v = src[t];
        v.x *= m; v.y *= m; v.z *= m; v.w *= m;
        dst[t] = v;
    }
}

// residual + layernorm + mask, in place into y2. 256 threads, one row per block.
__global__ void k_ln(float* __restrict__ y2, const float* __restrict__ x0,
                     const int* __restrict__ mask,
                     const float* __restrict__ g, const float* __restrict__ b) {
    int r = blockIdx.x;
    int tid = threadIdx.x;
    size_t base = (size_t)r * DV;
    float v0 = y2[base + tid]       + x0[base + tid];
    float v1 = y2[base + tid + 256] + x0[base + tid + 256];
    float s  = v0 + v1;
    float s2 = v0 * v0 + v1 * v1;
    __shared__ float sh1[8], sh2[8];
    __shared__ float s_mu, s_iv;
    #pragma unroll
    for (int o = 16; o > 0; o >>= 1) {
        s  += __shfl_down_sync(0xffffffffu, s,  o);
        s2 += __shfl_down_sync(0xffffffffu, s2, o);
    }
    if ((tid & 31) == 0) { sh1[tid >> 5] = s; sh2[tid >> 5] = s2; }
    __syncthreads();
    if (tid == 0) {
        float t1 = 0.f, t2 = 0.f;
        #pragma unroll
        for (int w = 0; w < 8; w++) { t1 += sh1[w]; t2 += sh2[w]; }
        float mu  = t1 * (1.0f / DV);
        float var = t2 * (1.0f / DV) - mu * mu;
        s_mu = mu;
        s_iv = rsqrtf(var + 1e-5f);
    }
    __syncthreads();
    float mu = s_mu, iv = s_iv;
    float m = (mask[r] != 0) ? 1.f : 0.f;
    y2[base + tid]       = ((v0 - mu) * iv * g[tid]       + b[tid])       * m;
    y2[base + tid + 256] = ((v1 - mu) * iv * g[tid + 256] + b[tid + 256]) * m;
}

// ---------------- SGEMM: C[m,n] = sum_k A[m,k] * B[n,k]   (NT) ----------------
// 128x128 tile, BK=16, 256 threads, 8x8 microtile. M,N %128==0, K %16==0.
template <int BIAS, int RELU>
__global__ void sgemm_nt(const float* __restrict__ A, const float* __restrict__ Bm,
                         const float* __restrict__ bias, float* __restrict__ C,
                         int M, int Ncols, int Kd) {
    __shared__ float As[16][129];
    __shared__ float Bs[16][129];
    const int tid = threadIdx.x;
    const int tx = tid & 15, ty = tid >> 4;
    const int bm = blockIdx.y << 7, bn = blockIdx.x << 7;
    const int ar = tid >> 2;           // 0..63
    const int ac = (tid & 3) << 2;     // 0,4,8,12
    float acc[8][8];
    #pragma unroll
    for (int i = 0; i < 8; i++)
        #pragma unroll
        for (int j = 0; j < 8; j++) acc[i][j] = 0.f;

    for (int k0 = 0; k0 < Kd; k0 += 16) {
        #pragma unroll
        for (int p = 0; p < 2; p++) {
            int rowa = bm + ar + (p << 6);
            float4 va = *(const float4*)(A + (size_t)rowa * Kd + k0 + ac);
            As[ac + 0][ar + (p << 6)] = va.x;
            As[ac + 1][ar + (p << 6)] = va.y;
            As[ac + 2][ar + (p << 6)] = va.z;
            As[ac + 3][ar + (p << 6)] = va.w;
            int rowb = bn + ar + (p << 6);
            float4 vb = *(const float4*)(Bm + (size_t)rowb * Kd + k0 + ac);
            Bs[ac + 0][ar + (p << 6)] = vb.x;
            Bs[ac + 1][ar + (p << 6)] = vb.y;
            Bs[ac + 2][ar + (p << 6)] = vb.z;
            Bs[ac + 3][ar + (p << 6)] = vb.w;
        }
        __syncthreads();
        #pragma unroll
        for (int k = 0; k < 16; k++) {
            float a[8], b[8];
            #pragma unroll
            for (int i = 0; i < 8; i++) a[i] = As[k][ty + (i << 4)];
            #pragma unroll
            for (int j = 0; j < 8; j++) b[j] = Bs[k][tx + (j << 4)];
            #pragma unroll
            for (int i = 0; i < 8; i++)
                #pragma unroll
                for (int j = 0; j < 8; j++)
                    acc[i][j] = fmaf(a[i], b[j], acc[i][j]);
        }
        __syncthreads();
    }
    #pragma unroll
    for (int i = 0; i < 8; i++) {
        int row = bm + ty + (i << 4);
        #pragma unroll
        for (int j = 0; j < 8; j++) {
            int col = bn + tx + (j << 4);
            float v = acc[i][j];
            if (BIAS) v += bias[col];
            if (RELU) v = fmaxf(v, 0.f);
            C[(size_t)row * Ncols + col] = v;
        }
    }
}

// ---------------- NN GEMM for AX = inv_i * (A_sub @ Xs + Xs_i) ----------------
// A: [NN,NN] row-major, B(Xs): [NN,DV] row-major. M=NN, Ncols=DV, Kd=NN.
__global__ void sgemm_nn_axs(const float* __restrict__ A, const float* __restrict__ Xs,
                             const float* __restrict__ invs, float* __restrict__ AX) {
    __shared__ float As[16][129];
    __shared__ float Bs[16][129];
    const int tid = threadIdx.x;
    const int tx = tid & 15, ty = tid >> 4;
    const int bm = blockIdx.y << 7, bn = blockIdx.x << 7;
    const int ar = tid >> 2;
    const int ac = (tid & 3) << 2;
    const int br = tid >> 5;           // 0..7
    const int bc = (tid & 31) << 2;    // 0..124
    float acc[8][8];
    #pragma unroll
    for (int i = 0; i < 8; i++)
        #pragma unroll
        for (int j = 0; j < 8; j++) acc[i][j] = 0.f;

    for (int k0 = 0; k0 < NN; k0 += 16) {
        #pragma unroll
        for (int p = 0; p < 2; p++) {
            int rowa = bm + ar + (p << 6);
            float4 va = *(const float4*)(A + (size_t)rowa * NN + k0 + ac);
            As[ac + 0][ar + (p << 6)] = va.x;
            As[ac + 1][ar + (p << 6)] = va.y;
            As[ac + 2][ar + (p << 6)] = va.z;
            As[ac + 3][ar + (p << 6)] = va.w;
            int kr = k0 + br + (p << 3);
            float4 vb = *(const float4*)(Xs + (size_t)kr * DV + bn + bc);
            Bs[br + (p << 3)][bc + 0] = vb.x;
            Bs[br + (p << 3)][bc + 1] = vb.y;
            Bs[br + (p << 3)][bc + 2] = vb.z;
            Bs[br + (p << 3)][bc + 3] = vb.w;
        }
        __syncthreads();
        #pragma unroll
        for (int k = 0; k < 16; k++) {
            float a[8], b[8];
            #pragma unroll
            for (int i = 0; i < 8; i++) a[i] = As[k][ty + (i << 4)];
            #pragma unroll
            for (int j = 0; j < 8; j++) b[j] = Bs[k][tx + (j << 4)];
            #pragma unroll
            for (int i = 0; i < 8; i++)
                #pragma unroll
                for (int j = 0; j < 8; j++)
                    acc[i][j] = fmaf(a[i], b[j], acc[i][j]);
        }
        __syncthreads();
    }
    #pragma unroll
    for (int i = 0; i < 8; i++) {
        int row = bm + ty + (i << 4);
        float iv = invs[row];
        #pragma unroll
        for (int j = 0; j < 8; j++) {
            int col = bn + tx + (j << 4);
            AX[(size_t)row * DV + col] = iv * (acc[i][j] + Xs[(size_t)row * DV + col]);
        }
    }
}

// ---------------- causal-conv as GEMM over K=1536 with shifted A rows ----------------
// out[r,o] = bias[o] + sum_{k,i} in[r+k-2, i] * w[k*512+i, o]   (rows clamped to batch)
template <int RELU>
__global__ void sgemm_conv(const float* __restrict__ in, const float* __restrict__ W,
                           const float* __restrict__ bias, float* __restrict__ out) {
    __shared__ float As[16][129];
    __shared__ float Bs[16][129];
    const int tid = threadIdx.x;
    const int tx = tid & 15, ty = tid >> 4;
    const int bm = blockIdx.y << 7, bn = blockIdx.x << 7;
    const int ar = tid >> 2;
    const int ac = (tid & 3) << 2;
    const int br = tid >> 5;
    const int bc = (tid & 31) << 2;
    float acc[8][8];
    #pragma unroll
    for (int i = 0; i < 8; i++)
        #pragma unroll
        for (int j = 0; j < 8; j++) acc[i][j] = 0.f;

    for (int k0 = 0; k0 < KCONV; k0 += 16) {
        int kk = k0 >> 9;                 // tap index: constant over this 16-wide tile
        int icol = (k0 & 511) + ac;
        #pragma unroll
        for (int p = 0; p < 2; p++) {
            int rg = bm + ar + (p << 6);
            int s = rg & (NS - 1);
            float4 va = make_float4(0.f, 0.f, 0.f, 0.f);
            if (s + kk >= 2)
                va = *(const float4*)(in + (size_t)(rg + kk - 2) * DV + icol);
            As[ac + 0][ar + (p << 6)] = va.x;
            As[ac + 1][ar + (p << 6)] = va.y;
            As[ac + 2][ar + (p << 6)] = va.z;
            As[ac + 3][ar + (p << 6)] = va.w;
            int kr = k0 + br + (p << 3);
            float4 vb = *(const float4*)(W + (size_t)kr * DV + bn + bc);
            Bs[br + (p << 3)][bc + 0] = vb.x;
            Bs[br + (p << 3)][bc + 1] = vb.y;
            Bs[br + (p << 3)][bc + 2] = vb.z;
            Bs[br + (p << 3)][bc + 3] = vb.w;
        }
        __syncthreads();
        #pragma unroll
        for (int k = 0; k < 16; k++) {
            float a[8], b[8];
            #pragma unroll
            for (int i = 0; i < 8; i++) a[i] = As[k][ty + (i << 4)];
            #pragma unroll
            for (int j = 0; j < 8; j++) b[j] = Bs[k][tx + (j << 4)];
            #pragma unroll
            for (int i = 0; i < 8; i++)
                #pragma unroll
                for (int j = 0; j < 8; j++)
                    acc[i][j] = fmaf(a[i], b[j], acc[i][j]);
        }
        __syncthreads();
    }
    #pragma unroll
    for (int i = 0; i < 8; i++) {
        int row = bm + ty + (i << 4);
        #pragma unroll
        for (int j = 0; j < 8; j++) {
            int col = bn + tx + (j << 4);
            float v = acc[i][j] + bias[col];
            if (RELU) v = fmaxf(v, 0.f);
            out[(size_t)row * DV + col] = v;
        }
    }
}

// ---------------- launch ----------------
extern "C" void kernel_launch(void* const* d_in, const int* in_sizes, int n_in,
                              void* d_out, int out_size) {
    const int*           x_in  = (const int*)d_in[0];
    const int*           mask  = (const int*)d_in[1];
    const int*           subn  = (const int*)d_in[2];
    const float*         A_sub = (const float*)d_in[3];
    const float*         embed = (const float*)d_in[4];
    const float*         c1w   = (const float*)d_in[5];
    const float*         c1b   = (const float*)d_in[6];
    const float*         c2w   = (const float*)d_in[7];
    const float*         c2b   = (const float*)d_in[8];
    const float*         lng   = (const float*)d_in[9];
    const float*         lnb   = (const float*)d_in[10];
    const float*         gcnw  = (const float*)d_in[11];
    const float*         gcnb  = (const float*)d_in[12];
    const float*         hpw   = (const float*)d_in[13];
    float*               out   = (float*)d_out;

    float *X0, *Y1, *Y2, *Xs, *AX, *Hc, *inv;
    cudaGetSymbolAddress((void**)&X0, g_X0);
    cudaGetSymbolAddress((void**)&Y1, g_Y1);
    cudaGetSymbolAddress((void**)&Y2, g_Y2);
    cudaGetSymbolAddress((void**)&Xs, g_Xs);
    cudaGetSymbolAddress((void**)&AX, g_AX);
    cudaGetSymbolAddress((void**)&Hc, g_Hc);
    cudaGetSymbolAddress((void**)&inv, g_inv);

    // ---- GCN branch ----
    k_deg<<<NN, 256>>>(A_sub, inv);
    k_gather_xs<<<NN, 128>>>(subn, embed, inv, Xs);
    sgemm_nn_axs<<<dim3(DV / 128, NN / 128), 256>>>(A_sub, Xs, inv, AX);
    sgemm_nt<1, 1><<<dim3(DV / 128, NN / 128), 256>>>(AX, gcnw, gcnb, Hc, NN, DV, DV);

    // ---- encoder branch ----
    k_embed_gather<<<NBS, 128>>>(x_in, mask, embed, X0);
    sgemm_conv<1><<<dim3(DV / 128, NBS / 128), 256>>>(X0, c1w, c1b, Y1);
    sgemm_conv<0><<<dim3(DV / 128, NBS / 128), 256>>>(Y1, c2w, c2b, Y2);
    k_ln<<<NBS, 256>>>(Y2, X0, mask, lng, lnb);
    sgemm_nt<0, 0><<<dim3(DV / 128, NBS / 128), 256>>>(Y2, hpw, nullptr, Y1, NBS, DV, DV);

    // ---- logits ----
    sgemm_nt<0, 0><<<dim3(NN / 128, NBS / 128), 256>>>(Y1, Hc, nullptr, out, NBS, NN, DV);
}

// round 4
// speedup vs baseline: 2.1838x; 2.1838x over previous
#include <cuda_runtime.h>
#include <cuda_bf16.h>
#include <mma.h>
#include <cstdint>

using namespace nvcuda;
typedef __nv_bfloat16 bf16;

#define DV    512
#define NB    32
#define NS    1024
#define NBS   (NB*NS)      // 32768
#define NN    2048
#define KCONV 1536         // 3*512

// ---------------- scratch (static device globals; no allocs) ----------------
__device__ float g_X0[NBS*DV];
__device__ float g_Y2[NBS*DV];
__device__ float g_Xs[NN*DV];
__device__ float g_inv[NN];

__device__ bf16 g_Ash[NN*NN],   g_Asl[NN*NN];     // split A_sub
__device__ bf16 g_XsTh[DV*NN],  g_XsTl[DV*NN];
__device__ bf16 g_AXh[NN*DV],   g_AXl[NN*DV];
__device__ bf16 g_Hch[NN*DV],   g_Hcl[NN*DV];
__device__ bf16 g_gwh[DV*DV],   g_gwl[DV*DV];
__device__ bf16 g_hph[DV*DV],   g_hpl[DV*DV];
__device__ bf16 g_w1Th[DV*KCONV], g_w1Tl[DV*KCONV];
__device__ bf16 g_w2Th[DV*KCONV], g_w2Tl[DV*KCONV];
__device__ bf16 g_X0h[NBS*DV],  g_X0l[NBS*DV];
__device__ bf16 g_Y1h[NBS*DV],  g_Y1l[NBS*DV];    // conv1 out; reused for h
__device__ bf16 g_Y2h[NBS*DV],  g_Y2l[NBS*DV];

// ---------------- helpers ----------------
__device__ __forceinline__ uint32_t smem_u32(const void* p) {
    uint32_t a;
    asm("{ .reg .u64 t; cvta.to.shared.u64 t, %1; cvt.u32.u64 %0, t; }" : "=r"(a) : "l"(p));
    return a;
}
__device__ __forceinline__ void cpa16(uint32_t d, const void* s, int sz) {
    asm volatile("cp.async.cg.shared.global [%0], [%1], 16, %2;" :: "r"(d), "l"(s), "r"(sz) : "memory");
}
__device__ __forceinline__ void split1(float v, bf16& h, bf16& l) {
    h = __float2bfloat16_rn(v);
    l = __float2bfloat16_rn(v - __bfloat162float(h));
}

// ---------------- small kernels ----------------
__global__ void k_deg(const float* __restrict__ A, float* __restrict__ invs) {
    int i = blockIdx.x, tid = threadIdx.x;
    float s = 0.f;
    const float* row = A + (size_t)i * NN;
    for (int j = tid; j < NN; j += 256) s += row[j];
    __shared__ float sh[8];
    #pragma unroll
    for (int o = 16; o > 0; o >>= 1) s += __shfl_down_sync(0xffffffffu, s, o);
    if ((tid & 31) == 0) sh[tid >> 5] = s;
    __syncthreads();
    if (tid == 0) {
        float t = 0.f;
        #pragma unroll
        for (int w = 0; w < 8; w++) t += sh[w];
        t += 1.0f;
        t = fmaxf(t, 1e-6f);
        invs[i] = rsqrtf(t);
    }
}

__global__ void k_gather_xs(const int* __restrict__ sub_nodes, const float* __restrict__ embed,
                            const float* __restrict__ invs, float* __restrict__ Xs) {
    int j = blockIdx.x;
    int idx = sub_nodes[j];
    float sc = invs[j];
    const float4* src = (const float4*)(embed + (size_t)idx * DV);
    float4* dst = (float4*)(Xs + (size_t)j * DV);
    for (int t = threadIdx.x; t < DV / 4; t += blockDim.x) {
        float4 v = src[t];
        v.x *= sc; v.y *= sc; v.z *= sc; v.w *= sc;
        dst[t] = v;
    }
}

__global__ void k_split(const float4* __restrict__ src, bf16* __restrict__ h,
                        bf16* __restrict__ l, int n4) {
    int i = blockIdx.x * 256 + threadIdx.x;
    if (i >= n4) return;
    float4 v = src[i];
    bf16 h0, h1, h2, h3, l0, l1, l2, l3;
    split1(v.x, h0, l0); split1(v.y, h1, l1); split1(v.z, h2, l2); split1(v.w, h3, l3);
    __nv_bfloat162* ph = (__nv_bfloat162*)h;
    __nv_bfloat162* pl = (__nv_bfloat162*)l;
    ph[2*i]   = __halves2bfloat162(h0, h1);
    ph[2*i+1] = __halves2bfloat162(h2, h3);
    pl[2*i]   = __halves2bfloat162(l0, l1);
    pl[2*i+1] = __halves2bfloat162(l2, l3);
}

// transpose + split: in[R,C] f32 -> out hi/lo [C,R] bf16
__global__ void k_transpose_split(const float* __restrict__ in, bf16* __restrict__ oh,
                                  bf16* __restrict__ ol, int R, int C) {
    __shared__ float t[32][33];
    int c0 = blockIdx.x * 32, r0 = blockIdx.y * 32;
    #pragma unroll
    for (int j = 0; j < 32; j += 8)
        t[threadIdx.y + j][threadIdx.x] = in[(size_t)(r0 + threadIdx.y + j) * C + c0 + threadIdx.x];
    __syncthreads();
    #pragma unroll
    for (int j = 0; j < 32; j += 8) {
        float v = t[threadIdx.x][threadIdx.y + j];
        bf16 h, l; split1(v, h, l);
        size_t o = (size_t)(c0 + threadIdx.y + j) * R + r0 + threadIdx.x;
        oh[o] = h; ol[o] = l;
    }
}

__global__ void k_embed_gather(const int* __restrict__ x_in, const int* __restrict__ mask,
                               const float* __restrict__ embed, float* __restrict__ X0,
                               bf16* __restrict__ X0h, bf16* __restrict__ X0l) {
    int r = blockIdx.x;
    int idx = x_in[r];
    float m = (mask[r] != 0) ? 1.f : 0.f;
    const float4* src = (const float4*)(embed + (size_t)idx * DV);
    float4* dst = (float4*)(X0 + (size_t)r * DV);
    for (int t = threadIdx.x; t < DV / 4; t += blockDim.x) {
        float4 v = src[t];
        v.x *= m; v.y *= m; v.z *= m; v.w *= m;
        dst[t] = v;
        bf16 h0, h1, h2, h3, l0, l1, l2, l3;
        split1(v.x, h0, l0); split1(v.y, h1, l1); split1(v.z, h2, l2); split1(v.w, h3, l3);
        size_t o = ((size_t)r * DV) / 2 + 2 * t;
        ((__nv_bfloat162*)X0h)[o]   = __halves2bfloat162(h0, h1);
        ((__nv_bfloat162*)X0h)[o+1] = __halves2bfloat162(h2, h3);
        ((__nv_bfloat162*)X0l)[o]   = __halves2bfloat162(l0, l1);
        ((__nv_bfloat162*)X0l)[o+1] = __halves2bfloat162(l2, l3);
    }
}

// residual + layernorm + mask; outputs split bf16 hi/lo
__global__ void k_ln(const float* __restrict__ y2, const float* __restrict__ x0,
                     const int* __restrict__ mask,
                     const float* __restrict__ g, const float* __restrict__ b,
                     bf16* __restrict__ oh, bf16* __restrict__ ol) {
    int r = blockIdx.x, tid = threadIdx.x;
    size_t base = (size_t)r * DV;
    float v0 = y2[base + tid]       + x0[base + tid];
    float v1 = y2[base + tid + 256] + x0[base + tid + 256];
    float s = v0 + v1, s2 = v0 * v0 + v1 * v1;
    __shared__ float sh1[8], sh2[8];
    __shared__ float s_mu, s_iv;
    #pragma unroll
    for (int o = 16; o > 0; o >>= 1) {
        s  += __shfl_down_sync(0xffffffffu, s,  o);
        s2 += __shfl_down_sync(0xffffffffu, s2, o);
    }
    if ((tid & 31) == 0) { sh1[tid >> 5] = s; sh2[tid >> 5] = s2; }
    __syncthreads();
    if (tid == 0) {
        float t1 = 0.f, t2 = 0.f;
        #pragma unroll
        for (int w = 0; w < 8; w++) { t1 += sh1[w]; t2 += sh2[w]; }
        float mu = t1 * (1.0f / DV);
        float var = t2 * (1.0f / DV) - mu * mu;
        s_mu = mu; s_iv = rsqrtf(var + 1e-5f);
    }
    __syncthreads();
    float mu = s_mu, iv = s_iv;
    float m = (mask[r] != 0) ? 1.f : 0.f;
    float o0 = ((v0 - mu) * iv * g[tid]       + b[tid])       * m;
    float o1 = ((v1 - mu) * iv * g[tid + 256] + b[tid + 256]) * m;
    bf16 h, l;
    split1(o0, h, l); oh[base + tid] = h;       ol[base + tid] = l;
    split1(o1, h, l); oh[base + tid + 256] = h; ol[base + tid + 256] = l;
}

// ---------------- bf16 3-pass GEMM on legacy tensor cores ----------------
// C[m,n] = sum_k A[m,k]*Bt[n,k] with A,Bt given as bf16 hi/lo pairs.
// 128x128 tile, BK=32, 256 threads, warp tile 32x64, 3-stage cp.async pipeline.
// MODE: 0=NT (lda), 1=CONV (lda=512, tap-shifted rows over K=1536)
// EPI:  0=none, 1=bias, 2=bias+relu, 3=axs: inv[row]*(acc + aux[row*512+col])
// OUT:  0=f32 to Cf, 1=bf16 hi/lo to Chi/Clo
#define STG   40960
#define SMEMSZ (3*STG)

template <int MODE, int EPI, int OUT>
__global__ void __launch_bounds__(256)
mma_gemm(const bf16* __restrict__ Ah, const bf16* __restrict__ Al,
         const bf16* __restrict__ Bh, const bf16* __restrict__ Bl,
         const float* __restrict__ aux, const float* __restrict__ invs,
         float* __restrict__ Cf, bf16* __restrict__ Chi, bf16* __restrict__ Clo,
         int Ncols, int Kd, int lda) {
    extern __shared__ __align__(128) char smem[];
    uint32_t sb = smem_u32(smem);
    const int tid = threadIdx.x;
    const int bm = blockIdx.y << 7, bn = blockIdx.x << 7;
    const int w = tid >> 5;
    const int rm = (w >> 1) << 5;   // warp row base (0,32,64,96)
    const int cn = (w & 1) << 6;    // warp col base (0,64)

    wmma::fragment<wmma::accumulator, 16, 16, 16, float> acc[2][4];
    #pragma unroll
    for (int mt = 0; mt < 2; mt++)
        #pragma unroll
        for (int nt = 0; nt < 4; nt++) wmma::fill_fragment(acc[mt][nt], 0.f);

    const int nch = Kd >> 5;

    auto issue = [&](int ch) {
        int k0 = ch << 5;
        uint32_t st = sb + (uint32_t)(ch % 3) * STG;
        #pragma unroll
        for (int t = 0; t < 2; t++) {
            int c = tid + (t << 8);
            int row = c >> 2;
            int col8 = (c & 3) << 3;
            uint32_t doff = (uint32_t)row * 80u + (uint32_t)((c & 3) << 4);
            if (MODE == 0) {
                size_t so = (size_t)(bm + row) * lda + k0 + col8;
                cpa16(st + doff,          Ah + so, 16);
                cpa16(st + 10240 + doff,  Al + so, 16);
            } else {
                int kk = k0 >> 9;
                int icol = (k0 & 511) + col8;
                int rg = bm + row;
                int valid = ((rg & (NS - 1)) + kk) >= 2;
                size_t so = (size_t)(valid ? rg + kk - 2 : rg) * 512 + icol;
                int sz = valid ? 16 : 0;
                cpa16(st + doff,          Ah + so, sz);
                cpa16(st + 10240 + doff,  Al + so, sz);
            }
            size_t sB = (size_t)(bn + row) * Kd + k0 + col8;
            cpa16(st + 20480 + doff, Bh + sB, 16);
            cpa16(st + 30720 + doff, Bl + sB, 16);
        }
        asm volatile("cp.async.commit_group;" ::: "memory");
    };

    issue(0);
    if (nch > 1) issue(1);

    for (int ch = 0; ch < nch; ch++) {
        __syncthreads();   // all warps done with buffer (ch+2)%3 from chunk ch-1
        if (ch + 2 < nch) {
            issue(ch + 2);
            asm volatile("cp.async.wait_group 2;" ::: "memory");
        } else if (ch + 1 < nch) {
            asm volatile("cp.async.wait_group 1;" ::: "memory");
        } else {
            asm volatile("cp.async.wait_group 0;" ::: "memory");
        }
        __syncthreads();

        const bf16* pAh = (const bf16*)(smem + (ch % 3) * STG);
        const bf16* pAl = pAh + 5120;
        const bf16* pBh = pAh + 10240;
        const bf16* pBl = pAh + 15360;
        #pragma unroll
        for (int ks = 0; ks < 32; ks += 16) {
            wmma::fragment<wmma::matrix_a, 16, 16, 16, bf16, wmma::row_major> fah[2], fal[2];
            wmma::fragment<wmma::matrix_b, 16, 16, 16, bf16, wmma::col_major> fbh[4], fbl[4];
            #pragma unroll
            for (int mt = 0; mt < 2; mt++) {
                wmma::load_matrix_sync(fah[mt], pAh + (rm + mt * 16) * 40 + ks, 40);
                wmma::load_matrix_sync(fal[mt], pAl + (rm + mt * 16) * 40 + ks, 40);
            }
            #pragma unroll
            for (int nt = 0; nt < 4; nt++) {
                wmma::load_matrix_sync(fbh[nt], pBh + (cn + nt * 16) * 40 + ks, 40);
                wmma::load_matrix_sync(fbl[nt], pBl + (cn + nt * 16) * 40 + ks, 40);
            }
            #pragma unroll
            for (int mt = 0; mt < 2; mt++)
                #pragma unroll
                for (int nt = 0; nt < 4; nt++) {
                    wmma::mma_sync(acc[mt][nt], fah[mt], fbh[nt], acc[mt][nt]);
                    wmma::mma_sync(acc[mt][nt], fah[mt], fbl[nt], acc[mt][nt]);
                    wmma::mma_sync(acc[mt][nt], fal[mt], fbh[nt], acc[mt][nt]);
                }
        }
    }

    // ---- epilogue via smem ----
    __syncthreads();
    float* Cbuf = (float*)smem;
    #pragma unroll
    for (int mt = 0; mt < 2; mt++)
        #pragma unroll
        for (int nt = 0; nt < 4; nt++)
            wmma::store_matrix_sync(Cbuf + (rm + mt * 16) * 132 + cn + nt * 16,
                                    acc[mt][nt], 132, wmma::mem_row_major);
    __syncthreads();

    int row = tid >> 1;
    int cp = (tid & 1) << 6;
    int grow = bm + row;
    float ivv = (EPI == 3) ? invs[grow] : 0.f;
    #pragma unroll
    for (int j = 0; j < 64; j += 4) {
        int col = cp + j;
        float v0 = Cbuf[row * 132 + col + 0];
        float v1 = Cbuf[row * 132 + col + 1];
        float v2 = Cbuf[row * 132 + col + 2];
        float v3 = Cbuf[row * 132 + col + 3];
        if (EPI == 1 || EPI == 2) {
            float4 bi = *(const float4*)(aux + bn + col);
            v0 += bi.x; v1 += bi.y; v2 += bi.z; v3 += bi.w;
            if (EPI == 2) {
                v0 = fmaxf(v0, 0.f); v1 = fmaxf(v1, 0.f);
                v2 = fmaxf(v2, 0.f); v3 = fmaxf(v3, 0.f);
            }
        } else if (EPI == 3) {
            float4 xs = *(const float4*)(aux + (size_t)grow * 512 + bn + col);
            v0 = ivv * (v0 + xs.x); v1 = ivv * (v1 + xs.y);
            v2 = ivv * (v2 + xs.z); v3 = ivv * (v3 + xs.w);
        }
        size_t off = (size_t)grow * Ncols + bn + col;
        if (OUT == 0) {
            *(float4*)(Cf + off) = make_float4(v0, v1, v2, v3);
        } else {
            bf16 h0, h1, h2, h3, l0, l1, l2, l3;
            split1(v0, h0, l0); split1(v1, h1, l1);
            split1(v2, h2, l2); split1(v3, h3, l3);
            __nv_bfloat162* ph = (__nv_bfloat162*)(Chi + off);
            __nv_bfloat162* pl = (__nv_bfloat162*)(Clo + off);
            ph[0] = __halves2bfloat162(h0, h1); ph[1] = __halves2bfloat162(h2, h3);
            pl[0] = __halves2bfloat162(l0, l1); pl[1] = __halves2bfloat162(l2, l3);
        }
    }
}

// ---------------- launch ----------------
extern "C" void kernel_launch(void* const* d_in, const int* in_sizes, int n_in,
                              void* d_out, int out_size) {
    const int*   x_in  = (const int*)d_in[0];
    const int*   mask  = (const int*)d_in[1];
    const int*   subn  = (const int*)d_in[2];
    const float* A_sub = (const float*)d_in[3];
    const float* embed = (const float*)d_in[4];
    const float* c1w   = (const float*)d_in[5];
    const float* c1b   = (const float*)d_in[6];
    const float* c2w   = (const float*)d_in[7];
    const float* c2b   = (const float*)d_in[8];
    const float* lng   = (const float*)d_in[9];
    const float* lnb   = (const float*)d_in[10];
    const float* gcnw  = (const float*)d_in[11];
    const float* gcnb  = (const float*)d_in[12];
    const float* hpw   = (const float*)d_in[13];
    float*       out   = (float*)d_out;

    float *X0, *Y2, *Xs, *inv;
    bf16 *Ash, *Asl, *XsTh, *XsTl, *AXh, *AXl, *Hch, *Hcl, *gwh, *gwl, *hph, *hpl;
    bf16 *w1Th, *w1Tl, *w2Th, *w2Tl, *X0h, *X0l, *Y1h, *Y1l, *Y2h, *Y2l;
    cudaGetSymbolAddress((void**)&X0,  g_X0);
    cudaGetSymbolAddress((void**)&Y2,  g_Y2);
    cudaGetSymbolAddress((void**)&Xs,  g_Xs);
    cudaGetSymbolAddress((void**)&inv, g_inv);
    cudaGetSymbolAddress((void**)&Ash, g_Ash);   cudaGetSymbolAddress((void**)&Asl, g_Asl);
    cudaGetSymbolAddress((void**)&XsTh, g_XsTh); cudaGetSymbolAddress((void**)&XsTl, g_XsTl);
    cudaGetSymbolAddress((void**)&AXh, g_AXh);   cudaGetSymbolAddress((void**)&AXl, g_AXl);
    cudaGetSymbolAddress((void**)&Hch, g_Hch);   cudaGetSymbolAddress((void**)&Hcl, g_Hcl);
    cudaGetSymbolAddress((void**)&gwh, g_gwh);   cudaGetSymbolAddress((void**)&gwl, g_gwl);
    cudaGetSymbolAddress((void**)&hph, g_hph);   cudaGetSymbolAddress((void**)&hpl, g_hpl);
    cudaGetSymbolAddress((void**)&w1Th, g_w1Th); cudaGetSymbolAddress((void**)&w1Tl, g_w1Tl);
    cudaGetSymbolAddress((void**)&w2Th, g_w2Th); cudaGetSymbolAddress((void**)&w2Tl, g_w2Tl);
    cudaGetSymbolAddress((void**)&X0h, g_X0h);   cudaGetSymbolAddress((void**)&X0l, g_X0l);
    cudaGetSymbolAddress((void**)&Y1h, g_Y1h);   cudaGetSymbolAddress((void**)&Y1l, g_Y1l);
    cudaGetSymbolAddress((void**)&Y2h, g_Y2h);   cudaGetSymbolAddress((void**)&Y2l, g_Y2l);

    cudaFuncSetAttribute(mma_gemm<0,3,1>, cudaFuncAttributeMaxDynamicSharedMemorySize, SMEMSZ);
    cudaFuncSetAttribute(mma_gemm<0,2,1>, cudaFuncAttributeMaxDynamicSharedMemorySize, SMEMSZ);
    cudaFuncSetAttribute(mma_gemm<1,2,1>, cudaFuncAttributeMaxDynamicSharedMemorySize, SMEMSZ);
    cudaFuncSetAttribute(mma_gemm<1,1,0>, cudaFuncAttributeMaxDynamicSharedMemorySize, SMEMSZ);
    cudaFuncSetAttribute(mma_gemm<0,0,1>, cudaFuncAttributeMaxDynamicSharedMemorySize, SMEMSZ);
    cudaFuncSetAttribute(mma_gemm<0,0,0>, cudaFuncAttributeMaxDynamicSharedMemorySize, SMEMSZ);

    dim3 t32(32, 8);

    // ---- GCN branch ----
    k_deg<<<NN, 256>>>(A_sub, inv);
    k_gather_xs<<<NN, 128>>>(subn, embed, inv, Xs);
    k_transpose_split<<<dim3(DV/32, NN/32), t32>>>(Xs, XsTh, XsTl, NN, DV);
    k_split<<<NN*NN/4/256, 256>>>((const float4*)A_sub, Ash, Asl, NN*NN/4);
    // AX = inv_i * (A_sub @ Xs + Xs_i)
    mma_gemm<0,3,1><<<dim3(DV/128, NN/128), 256, SMEMSZ>>>(
        Ash, Asl, XsTh, XsTl, Xs, inv, nullptr, AXh, AXl, DV, NN, NN);
    k_split<<<DV*DV/4/256, 256>>>((const float4*)gcnw, gwh, gwl, DV*DV/4);
    // Hc = relu(AX @ gcnw^T + gcnb)
    mma_gemm<0,2,1><<<dim3(DV/128, NN/128), 256, SMEMSZ>>>(
        AXh, AXl, gwh, gwl, gcnb, nullptr, nullptr, Hch, Hcl, DV, DV, DV);

    // ---- encoder branch ----
    k_embed_gather<<<NBS, 128>>>(x_in, mask, embed, X0, X0h, X0l);
    k_transpose_split<<<dim3(DV/32, KCONV/32), t32>>>(c1w, w1Th, w1Tl, KCONV, DV);
    k_transpose_split<<<dim3(DV/32, KCONV/32), t32>>>(c2w, w2Th, w2Tl, KCONV, DV);
    mma_gemm<1,2,1><<<dim3(DV/128, NBS/128), 256, SMEMSZ>>>(
        X0h, X0l, w1Th, w1Tl, c1b, nullptr, nullptr, Y1h, Y1l, DV, KCONV, 512);
    mma_gemm<1,1,0><<<dim3(DV/128, NBS/128), 256, SMEMSZ>>>(
        Y1h, Y1l, w2Th, w2Tl, c2b, nullptr, Y2, nullptr, nullptr, DV, KCONV, 512);
    k_ln<<<NBS, 256>>>(Y2, X0, mask, lng, lnb, Y2h, Y2l);
    k_split<<<DV*DV/4/256, 256>>>((const float4*)hpw, hph, hpl, DV*DV/4);
    // h = y @ hpw^T  (into Y1h/Y1l, dead after conv2)
    mma_gemm<0,0,1><<<dim3(DV/128, NBS/128), 256, SMEMSZ>>>(
        Y2h, Y2l, hph, hpl, nullptr, nullptr, nullptr, Y1h, Y1l, DV, DV, DV);

    // ---- logits = h @ Hc^T ----
    mma_gemm<0,0,0><<<dim3(NN/128, NBS/128), 256, SMEMSZ>>>(
        Y1h, Y1l, Hch, Hcl, nullptr, nullptr, out, nullptr, nullptr, NN, DV, DV);
}